// round 5
// baseline (speedup 1.0000x reference)
#include <cuda_runtime.h>
#include <cstdint>

// ---------------------------------------------------------------------------
// starConvexLoss — R4: LDG.128 row-pairs, no atomics, 2 launches
// ---------------------------------------------------------------------------

#define C_DIM 10
#define TPB   256
#define SPG   16        // s-values per block (grid.y = S/SPG)
#define MAXS  256
#define MAXBLK 256

// per-(s, block-x) partials — fully overwritten every run, no init needed
static __device__ float g_pw [MAXS * MAXBLK];
static __device__ float g_pwt[MAXS * MAXBLK];
static __device__ float g_pn2[MAXS * MAXBLK];
static __device__ float g_pwstar[MAXBLK];

// ---- fast math --------------------------------------------------------------
__device__ __forceinline__ float ex2a(float x) {
    float r; asm("ex2.approx.f32 %0, %1;" : "=f"(r) : "f"(x)); return r;
}
__device__ __forceinline__ float lg2a(float x) {
    float r; asm("lg2.approx.f32 %0, %1;" : "=f"(r) : "f"(x)); return r;
}
__device__ __forceinline__ float rcpa(float x) {
    float r; asm("rcp.approx.f32 %0, %1;" : "=f"(r) : "f"(x)); return r;
}

// ---- packed f32x2 (Blackwell) -------------------------------------------------
typedef unsigned long long u64;
__device__ __forceinline__ u64 fma2(u64 a, u64 b, u64 c) {
    u64 d; asm("fma.rn.f32x2 %0, %1, %2, %3;" : "=l"(d) : "l"(a), "l"(b), "l"(c)); return d;
}
__device__ __forceinline__ u64 add2(u64 a, u64 b) {
    u64 d; asm("add.rn.f32x2 %0, %1, %2;" : "=l"(d) : "l"(a), "l"(b)); return d;
}
__device__ __forceinline__ u64 mul2(u64 a, u64 b) {
    u64 d; asm("mul.rn.f32x2 %0, %1, %2;" : "=l"(d) : "l"(a), "l"(b)); return d;
}
__device__ __forceinline__ u64 pk(float x, float y) {
    u64 d; asm("mov.b64 %0, {%1, %2};" : "=l"(d) : "f"(x), "f"(y)); return d;
}
__device__ __forceinline__ float2 upk(u64 v) {
    float2 f; asm("mov.b64 {%0, %1}, %2;" : "=f"(f.x), "=f"(f.y) : "l"(v)); return f;
}

#define KH   0.7213475204444817f     // 0.5 * log2(e)
#define L2E  1.4426950408889634f
#define LN2  0.6931471805599453f
#define EM1  1.7182818284590452f     // e - 1

// ---- per-row soft-CE core: packed exp(n/2)/exp(n) dots against logp ---------
__device__ __forceinline__ void rowCE(
    const u64 nvp[C_DIM / 2], const u64 lp[C_DIM / 2],
    float lpt, float ntc, u64& n2p, float& wr, float& wtr) {
    u64 sep = 0ull, dotp = 0ull, selp = 0ull, dotlp = 0ull;
    #pragma unroll
    for (int k = 0; k < C_DIM / 2; k++) {
        float2 a = upk(nvp[k]);
        float eh0 = ex2a(a.x * KH);            // exp(0.5 n)
        float eh1 = ex2a(a.y * KH);
        u64 ehp = pk(eh0, eh1);
        u64 ep  = mul2(ehp, ehp);              // exp(n)
        sep   = add2(sep, ep);
        dotp  = fma2(ep,  lp[k], dotp);
        selp  = add2(selp, ehp);
        dotlp = fma2(ehp, lp[k], dotlp);
        n2p   = fma2(nvp[k], nvp[k], n2p);
    }
    float2 v;
    v = upk(sep);   float se   = v.x + v.y;
    v = upk(dotp);  float dot  = v.x + v.y;
    v = upk(selp);  float sel  = v.x + v.y;
    v = upk(dotlp); float dotl = v.x + v.y;

    float eht = ex2a(ntc * KH);
    float et  = eht * eht;
    se   = fmaf(EM1, et,  se);   dot  = fmaf(EM1 * et,  lpt, dot);
    sel  = fmaf(EM1, eht, sel);  dotl = fmaf(EM1 * eht, lpt, dotl);

    float r = rcpa(se * sel);                  // one rcp serves both ratios
    wr  = dot  * sel * r;
    wtr = dotl * se  * r;
}

// ---- inline log-softmax of one pred row -> packed logp + logp[target] -------
__device__ __forceinline__ void rowLogp(
    const float* __restrict__ pred, int b, int t,
    u64 lp[C_DIM / 2], float& lpt) {
    float p[C_DIM];
    const float2* pr = (const float2*)pred + (size_t)b * (C_DIM / 2);
    #pragma unroll
    for (int k = 0; k < C_DIM / 2; k++) {
        float2 v = __ldg(pr + k); p[2 * k] = v.x; p[2 * k + 1] = v.y;
    }
    float m = p[0];
    #pragma unroll
    for (int c = 1; c < C_DIM; c++) m = fmaxf(m, p[c]);
    float sum = 0.f;
    #pragma unroll
    for (int c = 0; c < C_DIM; c++) sum += ex2a((p[c] - m) * L2E);
    float lse = fmaf(lg2a(sum), LN2, m);
    #pragma unroll
    for (int k = 0; k < C_DIM / 2; k++)
        lp[k] = pk(p[2 * k] - lse, p[2 * k + 1] - lse);
    lpt = __ldg(pred + (size_t)b * C_DIM + t) - lse;
}

// ---- main kernel: row-pair per thread, LDG.128, per-block partials -----------
__global__ void __launch_bounds__(TPB, 2) k_main(
    const float* __restrict__ pred, const int* __restrict__ targets,
    const float* __restrict__ noise, int B, int S) {

    int nblk = gridDim.x;
    int pi_raw = blockIdx.x * TPB + threadIdx.x;       // row-pair index
    int nPairs = B >> 1;
    int pi = min(pi_raw, nPairs - 1);
    int b0 = 2 * pi, b1 = 2 * pi + 1;
    float valid = (pi_raw < nPairs) ? 1.f : 0.f;

    int s0   = blockIdx.y * SPG;
    int sEnd = min(s0 + SPG, S);

    int t0 = __ldg(targets + b0);
    int t1 = __ldg(targets + b1);

    u64 lp0[C_DIM / 2], lp1[C_DIM / 2];
    float lpt0, lpt1;
    rowLogp(pred, b0, t0, lp0, lpt0);
    rowLogp(pred, b1, t1, lp1, lpt1);

    __shared__ float sm[2][3][TPB / 32];
    int lane = threadIdx.x & 31, w = threadIdx.x >> 5;

    // ---- wstar partial (only y==0 grid slice) ----
    if (blockIdx.y == 0) {
        float wp = -(lpt0 + lpt1) * valid;
        #pragma unroll
        for (int o = 16; o; o >>= 1) wp += __shfl_xor_sync(0xffffffffu, wp, o);
        if (lane == 0) sm[0][0][w] = wp;
        __syncthreads();
        if (w == 0) {
            float v = (lane < TPB / 32) ? sm[0][0][lane] : 0.f;
            #pragma unroll
            for (int o = 4; o; o >>= 1) v += __shfl_xor_sync(0xffffffffu, v, o);
            if (lane == 0) g_pwstar[blockIdx.x] = v;
        }
        __syncthreads();
    }

    // ---- s loop: 5 LDG.128 per thread covers the 80B row pair ----
    const float4* nrow = (const float4*)(noise) + ((size_t)s0 * B + (size_t)b0) * C_DIM / 4;
    const size_t sStride4 = (size_t)B * C_DIM / 4;     // float4 units per s

    float4 q[5];
    float nt0c, nt1c;
    #pragma unroll
    for (int k = 0; k < 5; k++) q[k] = __ldg(nrow + k);
    nt0c = __ldg((const float*)nrow + t0);
    nt1c = __ldg((const float*)nrow + C_DIM + t1);

    for (int s = s0; s < sEnd; s++) {
        // prefetch next s
        float4 qn[5]; float nt0n = 0.f, nt1n = 0.f;
        const float4* nxt = nrow + sStride4;
        if (s + 1 < sEnd) {
            #pragma unroll
            for (int k = 0; k < 5; k++) qn[k] = __ldg(nxt + k);
            nt0n = __ldg((const float*)nxt + t0);
            nt1n = __ldg((const float*)nxt + C_DIM + t1);
        }

        u64 n2p = 0ull;
        // row 0: q0, q1, q2.xy
        u64 nv[5];
        nv[0] = pk(q[0].x, q[0].y); nv[1] = pk(q[0].z, q[0].w);
        nv[2] = pk(q[1].x, q[1].y); nv[3] = pk(q[1].z, q[1].w);
        nv[4] = pk(q[2].x, q[2].y);
        float w0, wt0;
        rowCE(nv, lp0, lpt0, nt0c, n2p, w0, wt0);

        // row 1: q2.zw, q3, q4
        nv[0] = pk(q[2].z, q[2].w);
        nv[1] = pk(q[3].x, q[3].y); nv[2] = pk(q[3].z, q[3].w);
        nv[3] = pk(q[4].x, q[4].y); nv[4] = pk(q[4].z, q[4].w);
        float w1, wt1;
        rowCE(nv, lp1, lpt1, nt1c, n2p, w1, wt1);

        float2 nn = upk(n2p);
        float wr  = (w0  + w1 ) * valid;
        float wtr = (wt0 + wt1) * valid;
        float n2r = (nn.x + nn.y) * valid;

        // rotate prefetch
        #pragma unroll
        for (int k = 0; k < 5; k++) q[k] = qn[k];
        nt0c = nt0n; nt1c = nt1n;
        nrow = nxt;

        // block reduce (parity double-buffered smem, one barrier per s)
        #pragma unroll
        for (int o = 16; o; o >>= 1) {
            wr  += __shfl_xor_sync(0xffffffffu, wr,  o);
            wtr += __shfl_xor_sync(0xffffffffu, wtr, o);
            n2r += __shfl_xor_sync(0xffffffffu, n2r, o);
        }
        int par = s & 1;
        if (lane == 0) { sm[par][0][w] = wr; sm[par][1][w] = wtr; sm[par][2][w] = n2r; }
        __syncthreads();
        if (w == 0) {
            float va = (lane < TPB / 32) ? sm[par][0][lane] : 0.f;
            float vb = (lane < TPB / 32) ? sm[par][1][lane] : 0.f;
            float vc = (lane < TPB / 32) ? sm[par][2][lane] : 0.f;
            #pragma unroll
            for (int o = 4; o; o >>= 1) {
                va += __shfl_xor_sync(0xffffffffu, va, o);
                vb += __shfl_xor_sync(0xffffffffu, vb, o);
                vc += __shfl_xor_sync(0xffffffffu, vc, o);
            }
            if (lane == 0) {
                int idx = s * nblk + blockIdx.x;
                g_pw [idx] = va;
                g_pwt[idx] = vb;
                g_pn2[idx] = vc;
            }
        }
    }
}

// ---- finalize: thread-per-s over partials, fp64 combine -----------------------
__global__ void __launch_bounds__(128) k_final(
    float* __restrict__ out, int B, int S, int nblk) {
    int tid = threadIdx.x;
    __shared__ double sdw;
    __shared__ double sred[4];

    // wstar = sum of per-block partials / B
    {
        float wp = (tid < nblk) ? g_pwstar[tid] : 0.f;
        for (int j = tid + 128; j < nblk; j += 128) wp += g_pwstar[j];
        double d = (double)wp;
        #pragma unroll
        for (int o = 16; o; o >>= 1) d += __shfl_xor_sync(0xffffffffu, d, o);
        __shared__ double tmp[4];
        if ((tid & 31) == 0) tmp[tid >> 5] = d;
        __syncthreads();
        if (tid == 0) sdw = (tmp[0] + tmp[1] + tmp[2] + tmp[3]) / (double)B;
        __syncthreads();
    }
    double invB = 1.0 / (double)B;
    double wstar = sdw;

    double acc = 0.0;
    if (tid < S) {
        // reduce this s's nblk partials with float4 loads (contiguous)
        float sw = 0.f, swt = 0.f, sn2 = 0.f;
        const float4* pw  = (const float4*)(g_pw  + tid * nblk);
        const float4* pwt = (const float4*)(g_pwt + tid * nblk);
        const float4* pn2 = (const float4*)(g_pn2 + tid * nblk);
        int q = nblk >> 2;
        #pragma unroll 4
        for (int j = 0; j < q; j++) {
            float4 a = pw[j], b = pwt[j], c = pn2[j];
            sw  += (a.x + a.y) + (a.z + a.w);
            swt += (b.x + b.y) + (b.z + b.w);
            sn2 += (c.x + c.y) + (c.z + c.w);
        }
        double wv  = -(double)sw  * invB;
        double wtv = -(double)swt * invB;
        double n2  = (double)sn2;
        double sc1 = fmax(wstar - wtv, 0.0);
        double sc2 = fmax(wstar - wv + 0.05 * n2, 0.0);                      // MU*n2/2
        double sc3 = fmax(wtv - 0.5 * wstar + 0.5 * wv + 0.0125 * n2, 0.0);  // MU*LAM*(1-LAM)/2
        acc = sc1 + sc2 + sc3;
    }
    #pragma unroll
    for (int o = 16; o; o >>= 1) acc += __shfl_xor_sync(0xffffffffu, acc, o);
    if ((tid & 31) == 0) sred[tid >> 5] = acc;
    __syncthreads();
    if (tid == 0)
        out[0] = (float)(wstar + 0.05 * (sred[0] + sred[1] + sred[2] + sred[3]));  // RHO
}

// ---- launcher -------------------------------------------------------------------
extern "C" void kernel_launch(void* const* d_in, const int* in_sizes, int n_in,
                              void* d_out, int out_size) {
    const float* pred    = (const float*)d_in[0];
    const int*   targets = (const int*)d_in[1];
    const float* noise   = (const float*)d_in[2];
    float* out = (float*)d_out;

    int B = in_sizes[1];                       // 65536
    int S = in_sizes[2] / in_sizes[0];         // 128

    int nPairs = B / 2;
    int gx = (nPairs + TPB - 1) / TPB;         // 128
    int gy = (S + SPG - 1) / SPG;              // 8
    dim3 grid(gx, gy);
    k_main<<<grid, TPB>>>(pred, targets, noise, B, S);
    k_final<<<1, 128>>>(out, B, S, gx);
}